// round 14
// baseline (speedup 1.0000x reference)
#include <cuda_runtime.h>
#include <cuda_fp16.h>
#include <math.h>
#include <stdint.h>

// ---------------------------------------------------------------------------
// Problem constants
// ---------------------------------------------------------------------------
#define BATCH 8
#define SEQ   1024
#define HID   1024
#define NHEAD 16
#define HDIM  64
#define MROWS (BATCH * SEQ)   // 8192

// ---------------------------------------------------------------------------
// Scratch (device globals; no allocation allowed)
// ---------------------------------------------------------------------------
__device__ __half g_xh[MROWS * HID];
__device__ __half g_qh[MROWS * HID];
__device__ __half g_kh[MROWS * HID];
__device__ __half g_vh[MROWS * HID];
__device__ __half g_ch[MROWS * HID];
__device__ __half g_wt4[4 * HID * HID];   // transposed weights [N,K], 4 panels

// ---------------------------------------------------------------------------
// Helpers
// ---------------------------------------------------------------------------
__device__ __forceinline__ uint32_t smem_u32(const void* p) {
    uint32_t a;
    asm("{ .reg .u64 t; cvta.to.shared.u64 t, %1; cvt.u32.u64 %0, t; }"
        : "=r"(a) : "l"(p));
    return a;
}

#define SW128(o) ((o) ^ (((o) >> 3) & 0x70))

__device__ __forceinline__ void cp16(uint32_t smem, const void* g) {
    asm volatile("cp.async.cg.shared.global [%0], [%1], 16;" :: "r"(smem), "l"(g));
}
#define CP_COMMIT()  asm volatile("cp.async.commit_group;" ::: "memory")
#define CP_WAIT1()   asm volatile("cp.async.wait_group 1;" ::: "memory")
#define CP_WAIT0()   asm volatile("cp.async.wait_group 0;" ::: "memory")

__device__ __forceinline__ void ldsm4(uint32_t* r, uint32_t addr) {
    asm volatile("ldmatrix.sync.aligned.m8n8.x4.shared.b16 {%0,%1,%2,%3}, [%4];"
        : "=r"(r[0]), "=r"(r[1]), "=r"(r[2]), "=r"(r[3]) : "r"(addr));
}
__device__ __forceinline__ void ldsm4t(uint32_t* r, uint32_t addr) {
    asm volatile("ldmatrix.sync.aligned.m8n8.x4.trans.shared.b16 {%0,%1,%2,%3}, [%4];"
        : "=r"(r[0]), "=r"(r[1]), "=r"(r[2]), "=r"(r[3]) : "r"(addr));
}
__device__ __forceinline__ void mma16816(float* c, const uint32_t* a, const uint32_t* b) {
    asm volatile("mma.sync.aligned.m16n8k16.row.col.f32.f16.f16.f32 "
        "{%0,%1,%2,%3}, {%4,%5,%6,%7}, {%8,%9}, {%0,%1,%2,%3};"
        : "+f"(c[0]), "+f"(c[1]), "+f"(c[2]), "+f"(c[3])
        : "r"(a[0]), "r"(a[1]), "r"(a[2]), "r"(a[3]), "r"(b[0]), "r"(b[1]));
}
__device__ __forceinline__ float ex2(float x) {
    float y;
    asm("ex2.approx.f32 %0, %1;" : "=f"(y) : "f"(x));
    return y;
}

// ---------------------------------------------------------------------------
// Fused converts in ONE launch: grid.z 0..3 = weight transpose+convert,
// grid.z 4 = x fp32->fp16.
// ---------------------------------------------------------------------------
__global__ void convert_all(const float* __restrict__ x,
                            const float* __restrict__ W0, const float* __restrict__ W1,
                            const float* __restrict__ W2, const float* __restrict__ W3,
                            __half* __restrict__ xh, __half* __restrict__ t4)
{
    const int z = blockIdx.z;
    if (z == 4) {
        // x convert: 1024 blocks x 256 threads, stride loop over 2M float4
        const float4* in = (const float4*)x;
        __half2* out = (__half2*)xh;
        const int n4 = MROWS * HID / 4;
        int bid = blockIdx.y * 32 + blockIdx.x;
        int t = threadIdx.y * 32 + threadIdx.x;
        for (int i = bid * 256 + t; i < n4; i += 1024 * 256) {
            float4 v = in[i];
            out[2 * i]     = __floats2half2_rn(v.x, v.y);
            out[2 * i + 1] = __floats2half2_rn(v.z, v.w);
        }
        return;
    }

    __shared__ float t[32][33];
    const float* W = (z == 0) ? W0 : (z == 1) ? W1 : (z == 2) ? W2 : W3;
    __half* to = t4 + (size_t)z * HID * HID;

    int n0 = blockIdx.x * 32, k0 = blockIdx.y * 32;
    int tx = threadIdx.x, ty = threadIdx.y;
    #pragma unroll
    for (int r = 0; r < 32; r += 8)
        t[ty + r][tx] = W[(size_t)(k0 + ty + r) * HID + n0 + tx];
    __syncthreads();
    #pragma unroll
    for (int r = 0; r < 32; r += 8)
        to[(size_t)(n0 + ty + r) * HID + k0 + tx] = __float2half_rn(t[tx][ty + r]);
}

// ---------------------------------------------------------------------------
// GEMM machinery (single-term fp16, fp32 accumulate)
// CTA tile 128x64, K-chunk 64, double-buffered. 8 warps = 4(m) x 2(n).
// ---------------------------------------------------------------------------
#define GKC        64
#define NCHUNK     (HID / GKC)       // 16
#define OFF_B      16384
#define STAGE_BYTES 24576            // A 16K + B 8K
#define GEMM_SMEM  (2 * STAGE_BYTES) // 49152 (static)

__device__ __forceinline__ void gemm_mainloop(uint32_t sb, float c[2][4][4],
    const __half* __restrict__ A, const __half* __restrict__ B,
    int by, int bx, int tid, int lane, int wid)
{
    const int wm = (wid & 3) * 32;
    const int wn = (wid >> 2) * 32;

    const int a_r    = (lane & 7) + ((lane >> 3) & 1) * 8;
    const int a_kb16 = (lane >> 4) * 16;
    const int b_r4   = ((lane >> 4) & 1) * 8 + (lane & 7);
    const int b_kb16 = ((lane >> 3) & 1) * 16;

    // Precomputed per-thread load geometry (SW128 offsets + base pointers)
    uint32_t aso[4]; const __half* ap[4];
    #pragma unroll
    for (int r = 0; r < 4; r++) {
        int u = r * 256 + tid;
        int m = u >> 3, seg = u & 7;
        aso[r] = SW128((uint32_t)(m * 128 + seg * 16));
        ap[r]  = A + (size_t)(by * 128 + m) * HID + seg * 8;
    }
    uint32_t bso[2]; const __half* bp[2];
    #pragma unroll
    for (int r = 0; r < 2; r++) {
        int u = r * 256 + tid;
        int n = u >> 3, seg = u & 7;
        bso[r] = SW128((uint32_t)(n * 128 + seg * 16));
        bp[r]  = B + (size_t)(bx * 64 + n) * HID + seg * 8;
    }

    // Prologue: chunk 0
    #pragma unroll
    for (int r = 0; r < 4; r++) cp16(sb + aso[r], ap[r]);
    #pragma unroll
    for (int r = 0; r < 2; r++) cp16(sb + OFF_B + bso[r], bp[r]);
    CP_COMMIT();

    // Hoisted ldmatrix column constants (row&7 is loop-invariant per thread)
    uint32_t acol[4], bcol[4];
    #pragma unroll
    for (int ks = 0; ks < 4; ks++) {
        acol[ks] = (uint32_t)((ks * 32 + a_kb16) ^ ((a_r & 7) << 4));
        bcol[ks] = (uint32_t)((ks * 32 + b_kb16) ^ ((b_r4 & 7) << 4));
    }

    for (int ch = 0; ch < NCHUNK; ch++) {
        const uint32_t sbase = sb + (ch & 1) * STAGE_BYTES;

        if (ch + 1 < NCHUNK) {
            const uint32_t nb = sb + ((ch + 1) & 1) * STAGE_BYTES;
            const int k0 = (ch + 1) * GKC;
            #pragma unroll
            for (int r = 0; r < 4; r++) cp16(nb + aso[r], ap[r] + k0);
            #pragma unroll
            for (int r = 0; r < 2; r++) cp16(nb + OFF_B + bso[r], bp[r] + k0);
            CP_COMMIT();
            CP_WAIT1();
        } else {
            CP_WAIT0();
        }
        __syncthreads();

        const uint32_t ar0 = sbase + (uint32_t)((wm + a_r) * 128);
        const uint32_t br0 = sbase + OFF_B + (uint32_t)((wn + b_r4) * 128);

        #pragma unroll
        for (int ks = 0; ks < 4; ks++) {
            uint32_t Ah[2][4];
            ldsm4(Ah[0], ar0 + acol[ks]);
            ldsm4(Ah[1], ar0 + 2048 + acol[ks]);   // +16 rows

            #pragma unroll
            for (int ntp = 0; ntp < 2; ntp++) {
                uint32_t Bh[4];
                ldsm4(Bh, br0 + (uint32_t)(ntp * 2048) + bcol[ks]);
                #pragma unroll
                for (int half = 0; half < 2; half++) {
                    int nt = 2 * ntp + half;
                    mma16816(c[0][nt], Ah[0], Bh + 2 * half);
                    mma16816(c[1][nt], Ah[1], Bh + 2 * half);
                }
            }
        }

        __syncthreads();
    }
}

// Fused Q/K/V projection: grid.x = 48 (panel = bx>>4), fp16 output.
__global__ __launch_bounds__(256)
void gemm_qkv(const __half* __restrict__ A, const __half* __restrict__ wt4,
              const float* __restrict__ bq, const float* __restrict__ bk,
              const float* __restrict__ bv,
              __half* __restrict__ q, __half* __restrict__ k, __half* __restrict__ v)
{
    __shared__ __align__(128) char smem[GEMM_SMEM];
    uint32_t sb = smem_u32(smem);
    const int tid  = threadIdx.x;
    const int lane = tid & 31;
    const int wid  = tid >> 5;
    const int panel = blockIdx.x >> 4;
    const int bx    = blockIdx.x & 15;
    const int by    = blockIdx.y;

    const __half* B = wt4 + (size_t)panel * HID * HID;
    const float* bias = (panel == 0) ? bq : (panel == 1) ? bk : bv;
    __half* O = (panel == 0) ? q : (panel == 1) ? k : v;
    const float scale = (panel == 0) ? 0.125f * 1.44269504f : 1.0f;

    float c[2][4][4];
    #pragma unroll
    for (int mt = 0; mt < 2; mt++)
        #pragma unroll
        for (int nt = 0; nt < 4; nt++)
            #pragma unroll
            for (int i = 0; i < 4; i++) c[mt][nt][i] = 0.0f;

    gemm_mainloop(sb, c, A, B, by, bx, tid, lane, wid);

    const int wm = (wid & 3) * 32;
    const int wn = (wid >> 2) * 32;
    const int crow0 = by * 128 + wm + (lane >> 2);
    const int ccol0 = bx * 64 + wn + (lane & 3) * 2;
    #pragma unroll
    for (int nt = 0; nt < 4; nt++) {
        float2 bb = *(const float2*)&bias[ccol0 + nt * 8];
        #pragma unroll
        for (int mt = 0; mt < 2; mt++) {
            #pragma unroll
            for (int h = 0; h < 2; h++) {
                int row = crow0 + mt * 16 + h * 8;
                float vx = (c[mt][nt][2 * h + 0] + bb.x) * scale;
                float vy = (c[mt][nt][2 * h + 1] + bb.y) * scale;
                *(__half2*)&O[(size_t)row * HID + ccol0 + nt * 8] = __floats2half2_rn(vx, vy);
            }
        }
    }
}

// O-projection GEMM: fp32 output + bias.
__global__ __launch_bounds__(256)
void gemm_out(const __half* __restrict__ A, const __half* __restrict__ B,
              const float* __restrict__ bias, float* __restrict__ Cf)
{
    __shared__ __align__(128) char smem[GEMM_SMEM];
    uint32_t sb = smem_u32(smem);
    const int tid  = threadIdx.x;
    const int lane = tid & 31;
    const int wid  = tid >> 5;
    const int bx = blockIdx.x, by = blockIdx.y;

    float c[2][4][4];
    #pragma unroll
    for (int mt = 0; mt < 2; mt++)
        #pragma unroll
        for (int nt = 0; nt < 4; nt++)
            #pragma unroll
            for (int i = 0; i < 4; i++) c[mt][nt][i] = 0.0f;

    gemm_mainloop(sb, c, A, B, by, bx, tid, lane, wid);

    const int wm = (wid & 3) * 32;
    const int wn = (wid >> 2) * 32;
    const int crow0 = by * 128 + wm + (lane >> 2);
    const int ccol0 = bx * 64 + wn + (lane & 3) * 2;
    #pragma unroll
    for (int nt = 0; nt < 4; nt++) {
        float2 bb = *(const float2*)&bias[ccol0 + nt * 8];
        #pragma unroll
        for (int mt = 0; mt < 2; mt++) {
            #pragma unroll
            for (int h = 0; h < 2; h++) {
                int row = crow0 + mt * 16 + h * 8;
                float2 v;
                v.x = c[mt][nt][2 * h + 0] + bb.x;
                v.y = c[mt][nt][2 * h + 1] + bb.y;
                *(float2*)&Cf[(size_t)row * HID + ccol0 + nt * 8] = v;
            }
        }
    }
}

// ---------------------------------------------------------------------------
// fp16 tensor-core flash attention, 64-key tiles, double-buffered K/V.
// Per CTA: 128 queries x one (b,h). 8 warps x 16 query rows (256 threads).
// o-rescale skipped when running max unchanged (bitwise-identical math:
// multiply-by-1.0 == skip). ldmatrix addresses hoisted to loop constants.
// smem: Q 16K + 2 stages x (K 8K + V 8K) = 48K static.
// ---------------------------------------------------------------------------
#define KT     64
#define ATT_Q   0
#define ATT_STG0 16384
#define ATT_STG_SZ 16384
#define ATT_V_OFF 8192
#define ATT_SMEM 49152

__global__ __launch_bounds__(256, 2)
void flash_attn_mma(const __half* __restrict__ Q, const __half* __restrict__ K,
                    const __half* __restrict__ V, __half* __restrict__ C)
{
    __shared__ __align__(128) char smem[ATT_SMEM];
    uint32_t sb = smem_u32(smem);
    const int tid  = threadIdx.x;
    const int lane = tid & 31;
    const int wid  = tid >> 5;
    const int q0 = blockIdx.x * 128;
    const int h  = blockIdx.y;
    const int b  = blockIdx.z;

    const size_t qg  = ((size_t)(b * SEQ + q0)) * HID + h * HDIM;
    const size_t kvg = ((size_t)(b * SEQ)) * HID + h * HDIM;

    // ---- Q load ----
    {
        #pragma unroll
        for (int r = 0; r < 4; r++) {
            int u = r * 256 + tid;
            int row = u >> 3, seg = u & 7;
            uint32_t so = SW128((uint32_t)(row * 128 + seg * 16));
            cp16(sb + ATT_Q + so, Q + qg + (size_t)row * HID + seg * 8);
        }
    }
    CP_COMMIT();

    // K/V load geometry
    uint32_t kvso[2];
    const __half* kp[2];
    const __half* vp[2];
    #pragma unroll
    for (int r = 0; r < 2; r++) {
        int u = r * 256 + tid;
        int row = u >> 3, seg = u & 7;
        kvso[r] = SW128((uint32_t)(row * 128 + seg * 16));
        size_t off = kvg + (size_t)row * HID + seg * 8;
        kp[r] = K + off;
        vp[r] = V + off;
    }

    // KV tile 0 -> stage 0
    #pragma unroll
    for (int r = 0; r < 2; r++) {
        cp16(sb + ATT_STG0 + kvso[r], kp[r]);
        cp16(sb + ATT_STG0 + ATT_V_OFF + kvso[r], vp[r]);
    }
    CP_COMMIT();
    #pragma unroll
    for (int r = 0; r < 2; r++) { kp[r] += KT * HID; vp[r] += KT * HID; }

    const int wm = wid * 16;
    const int a_r    = (lane & 7) + ((lane >> 3) & 1) * 8;
    const int a_kb16 = (lane >> 4) * 16;
    const int b_r    = lane & 7;
    const int b_kb16 = ((lane >> 3) & 1) * 16;

    // Hoisted ldmatrix geometry:
    // K loads: row = ntp*16 + hi8 + b_r; row&7 == b_r -> col[kc] constant.
    uint32_t kcol[4];
    #pragma unroll
    for (int kc = 0; kc < 4; kc++)
        kcol[kc] = (uint32_t)((kc * 32 + b_kb16) ^ ((b_r & 7) << 4));
    const uint32_t krow0 = (uint32_t)((((lane >> 4) & 1) * 8 + b_r) * 128);
    // V loads (trans): row = kj*16 + (lane&15); row&7 == lane&7.
    uint32_t vcol[4];
    #pragma unroll
    for (int ntv = 0; ntv < 4; ntv++)
        vcol[ntv] = (uint32_t)((ntv * 32 + 16 * (lane >> 4)) ^ ((lane & 7) << 4));
    const uint32_t vrow0 = (uint32_t)((lane & 15) * 128);

    CP_WAIT1();              // Q resident
    __syncthreads();

    // Cache Q A-fragments
    uint32_t qh[4][4];
    #pragma unroll
    for (int kc = 0; kc < 4; kc++) {
        int row = wm + a_r;
        uint32_t col = (uint32_t)((kc * 32 + a_kb16) ^ ((row & 7) << 4));
        ldsm4(qh[kc], sb + ATT_Q + (uint32_t)(row * 128) + col);
    }

    float m0 = -INFINITY, m1 = -INFINITY, l0 = 0.0f, l1 = 0.0f;
    float o[8][4];
    #pragma unroll
    for (int nt = 0; nt < 8; nt++)
        #pragma unroll
        for (int i = 0; i < 4; i++) o[nt][i] = 0.0f;

    for (int kt = 0; kt < SEQ / KT; kt++) {
        if (kt + 1 < SEQ / KT) {
            const uint32_t nstg = sb + ATT_STG0 + ((kt + 1) & 1) * ATT_STG_SZ;
            #pragma unroll
            for (int r = 0; r < 2; r++) {
                cp16(nstg + kvso[r], kp[r]);
                cp16(nstg + ATT_V_OFF + kvso[r], vp[r]);
            }
            CP_COMMIT();
            #pragma unroll
            for (int r = 0; r < 2; r++) { kp[r] += KT * HID; vp[r] += KT * HID; }
            CP_WAIT1();
        } else {
            CP_WAIT0();
        }
        __syncthreads();

        const uint32_t stg = sb + ATT_STG0 + (kt & 1) * ATT_STG_SZ;
        const uint32_t kbase = stg + krow0;
        const uint32_t vbase = stg + ATT_V_OFF + vrow0;

        // ---- S = Q @ K^T ----
        float s[8][4];
        #pragma unroll
        for (int nt = 0; nt < 8; nt++)
            #pragma unroll
            for (int i = 0; i < 4; i++) s[nt][i] = 0.0f;

        #pragma unroll
        for (int kc = 0; kc < 4; kc++) {
            #pragma unroll
            for (int ntp = 0; ntp < 4; ntp++) {
                uint32_t kh[4];
                ldsm4(kh, kbase + (uint32_t)(ntp * 2048) + kcol[kc]);
                mma16816(s[2 * ntp],     qh[kc], kh);
                mma16816(s[2 * ntp + 1], qh[kc], kh + 2);
            }
        }

        // ---- Online softmax (base-2) ----
        float rmax0 = -INFINITY, rmax1 = -INFINITY;
        #pragma unroll
        for (int nt = 0; nt < 8; nt++) {
            rmax0 = fmaxf(rmax0, fmaxf(s[nt][0], s[nt][1]));
            rmax1 = fmaxf(rmax1, fmaxf(s[nt][2], s[nt][3]));
        }
        rmax0 = fmaxf(rmax0, __shfl_xor_sync(0xffffffffu, rmax0, 1));
        rmax0 = fmaxf(rmax0, __shfl_xor_sync(0xffffffffu, rmax0, 2));
        rmax1 = fmaxf(rmax1, __shfl_xor_sync(0xffffffffu, rmax1, 1));
        rmax1 = fmaxf(rmax1, __shfl_xor_sync(0xffffffffu, rmax1, 2));

        // Rescale only when max actually advanced (bitwise equal to the
        // unconditional version: f==1 multiply is skipped).
        if (rmax0 > m0) {
            float f0 = ex2(m0 - rmax0);
            m0 = rmax0;
            l0 *= f0;
            #pragma unroll
            for (int nt = 0; nt < 8; nt++) { o[nt][0] *= f0; o[nt][1] *= f0; }
        }
        if (rmax1 > m1) {
            float f1 = ex2(m1 - rmax1);
            m1 = rmax1;
            l1 *= f1;
            #pragma unroll
            for (int nt = 0; nt < 8; nt++) { o[nt][2] *= f1; o[nt][3] *= f1; }
        }

        float ls0 = 0.0f, ls1 = 0.0f;
        #pragma unroll
        for (int nt = 0; nt < 8; nt++) {
            s[nt][0] = ex2(s[nt][0] - m0);
            s[nt][1] = ex2(s[nt][1] - m0);
            s[nt][2] = ex2(s[nt][2] - m1);
            s[nt][3] = ex2(s[nt][3] - m1);
            ls0 += s[nt][0] + s[nt][1];
            ls1 += s[nt][2] + s[nt][3];
        }
        ls0 += __shfl_xor_sync(0xffffffffu, ls0, 1);
        ls0 += __shfl_xor_sync(0xffffffffu, ls0, 2);
        ls1 += __shfl_xor_sync(0xffffffffu, ls1, 1);
        ls1 += __shfl_xor_sync(0xffffffffu, ls1, 2);
        l0 += ls0;
        l1 += ls1;

        // ---- P pack + PV MMAs ----
        #pragma unroll
        for (int kj = 0; kj < 4; kj++) {
            uint32_t phi[4];
            #pragma unroll
            for (int half = 0; half < 2; half++) {
                int t = 2 * kj + half;
                __half2 h0 = __floats2half2_rn(s[t][0], s[t][1]);
                __half2 h1 = __floats2half2_rn(s[t][2], s[t][3]);
                phi[2 * half + 0] = *(uint32_t*)&h0;
                phi[2 * half + 1] = *(uint32_t*)&h1;
            }
            #pragma unroll
            for (int ntv = 0; ntv < 4; ntv++) {
                uint32_t vh[4];
                ldsm4t(vh, vbase + (uint32_t)(kj * 2048) + vcol[ntv]);
                mma16816(o[2 * ntv],     phi, vh);
                mma16816(o[2 * ntv + 1], phi, vh + 2);
            }
        }

        __syncthreads();
    }

    // ---- Finalize ----
    const float inv0 = 1.0f / l0, inv1 = 1.0f / l1;
    const int row0 = q0 + wm + (lane >> 2);
    const int colb = (lane & 3) * 2;
    #pragma unroll
    for (int nt = 0; nt < 8; nt++) {
        {
            size_t idx = ((size_t)(b * SEQ + row0)) * HID + h * HDIM + nt * 8 + colb;
            *(__half2*)&C[idx] = __floats2half2_rn(o[nt][0] * inv0, o[nt][1] * inv0);
        }
        {
            size_t idx = ((size_t)(b * SEQ + row0 + 8)) * HID + h * HDIM + nt * 8 + colb;
            *(__half2*)&C[idx] = __floats2half2_rn(o[nt][2] * inv1, o[nt][3] * inv1);
        }
    }
}

// ---------------------------------------------------------------------------
// Launch (no cudaFuncSetAttribute, no dynamic smem)
// ---------------------------------------------------------------------------
extern "C" void kernel_launch(void* const* d_in, const int* in_sizes, int n_in,
                              void* d_out, int out_size)
{
    const float* x  = (const float*)d_in[0];
    const float* Wq = (const float*)d_in[1];
    const float* bq = (const float*)d_in[2];
    const float* Wk = (const float*)d_in[3];
    const float* bk = (const float*)d_in[4];
    const float* Wv = (const float*)d_in[5];
    const float* bv = (const float*)d_in[6];
    const float* Wo = (const float*)d_in[7];
    const float* bo = (const float*)d_in[8];
    float* out = (float*)d_out;

    __half *xh, *qh, *kh, *vh, *ch, *wt4;
    cudaGetSymbolAddress((void**)&xh, g_xh);
    cudaGetSymbolAddress((void**)&qh, g_qh);
    cudaGetSymbolAddress((void**)&kh, g_kh);
    cudaGetSymbolAddress((void**)&vh, g_vh);
    cudaGetSymbolAddress((void**)&ch, g_ch);
    cudaGetSymbolAddress((void**)&wt4, g_wt4);

    dim3 cvg(HID / 32, HID / 32, 5);
    dim3 cvb(32, 8);
    convert_all<<<cvg, cvb>>>(x, Wq, Wk, Wv, Wo, xh, wt4);

    dim3 qkvgrid(48, MROWS / 128);   // (48, 64): 3 panels x 16 n-tiles
    gemm_qkv<<<qkvgrid, 256>>>(xh, wt4, bq, bk, bv, qh, kh, vh);

    dim3 agrid(SEQ / 128, NHEAD, BATCH);   // (8, 16, 8)
    flash_attn_mma<<<agrid, 256>>>(qh, kh, vh, ch);

    dim3 ogrid(HID / 64, MROWS / 128);    // (16, 64)
    gemm_out<<<ogrid, 256>>>(ch, wt4 + (size_t)3 * HID * HID, bo, out);
}

// round 17
// speedup vs baseline: 1.0071x; 1.0071x over previous
#include <cuda_runtime.h>
#include <cuda_fp16.h>
#include <math.h>
#include <stdint.h>

// ---------------------------------------------------------------------------
// Problem constants
// ---------------------------------------------------------------------------
#define BATCH 8
#define SEQ   1024
#define HID   1024
#define NHEAD 16
#define HDIM  64
#define MROWS (BATCH * SEQ)   // 8192

// ---------------------------------------------------------------------------
// Scratch (device globals; no allocation allowed)
// ---------------------------------------------------------------------------
__device__ __half g_xh[MROWS * HID];
__device__ __half g_qh[MROWS * HID];
__device__ __half g_kh[MROWS * HID];
__device__ __half g_vh[MROWS * HID];
__device__ __half g_ch[MROWS * HID];
__device__ __half g_wt4[4 * HID * HID];   // transposed weights [N,K], 4 panels

// ---------------------------------------------------------------------------
// Helpers
// ---------------------------------------------------------------------------
__device__ __forceinline__ uint32_t smem_u32(const void* p) {
    uint32_t a;
    asm("{ .reg .u64 t; cvta.to.shared.u64 t, %1; cvt.u32.u64 %0, t; }"
        : "=r"(a) : "l"(p));
    return a;
}

#define SW128(o) ((o) ^ (((o) >> 3) & 0x70))

__device__ __forceinline__ void cp16(uint32_t smem, const void* g) {
    asm volatile("cp.async.cg.shared.global [%0], [%1], 16;" :: "r"(smem), "l"(g));
}
#define CP_COMMIT()  asm volatile("cp.async.commit_group;" ::: "memory")
#define CP_WAIT1()   asm volatile("cp.async.wait_group 1;" ::: "memory")
#define CP_WAIT0()   asm volatile("cp.async.wait_group 0;" ::: "memory")

__device__ __forceinline__ void ldsm4(uint32_t* r, uint32_t addr) {
    asm volatile("ldmatrix.sync.aligned.m8n8.x4.shared.b16 {%0,%1,%2,%3}, [%4];"
        : "=r"(r[0]), "=r"(r[1]), "=r"(r[2]), "=r"(r[3]) : "r"(addr));
}
__device__ __forceinline__ void ldsm4t(uint32_t* r, uint32_t addr) {
    asm volatile("ldmatrix.sync.aligned.m8n8.x4.trans.shared.b16 {%0,%1,%2,%3}, [%4];"
        : "=r"(r[0]), "=r"(r[1]), "=r"(r[2]), "=r"(r[3]) : "r"(addr));
}
__device__ __forceinline__ void mma16816(float* c, const uint32_t* a, const uint32_t* b) {
    asm volatile("mma.sync.aligned.m16n8k16.row.col.f32.f16.f16.f32 "
        "{%0,%1,%2,%3}, {%4,%5,%6,%7}, {%8,%9}, {%0,%1,%2,%3};"
        : "+f"(c[0]), "+f"(c[1]), "+f"(c[2]), "+f"(c[3])
        : "r"(a[0]), "r"(a[1]), "r"(a[2]), "r"(a[3]), "r"(b[0]), "r"(b[1]));
}
__device__ __forceinline__ float ex2(float x) {
    float y;
    asm("ex2.approx.f32 %0, %1;" : "=f"(y) : "f"(x));
    return y;
}

// ---------------------------------------------------------------------------
// Fused converts in ONE launch: grid.z 0..3 = weight transpose+convert,
// grid.z 4 = x fp32->fp16.
// ---------------------------------------------------------------------------
__global__ void convert_all(const float* __restrict__ x,
                            const float* __restrict__ W0, const float* __restrict__ W1,
                            const float* __restrict__ W2, const float* __restrict__ W3,
                            __half* __restrict__ xh, __half* __restrict__ t4)
{
    const int z = blockIdx.z;
    if (z == 4) {
        const float4* in = (const float4*)x;
        __half2* out = (__half2*)xh;
        const int n4 = MROWS * HID / 4;
        int bid = blockIdx.y * 32 + blockIdx.x;
        int t = threadIdx.y * 32 + threadIdx.x;
        for (int i = bid * 256 + t; i < n4; i += 1024 * 256) {
            float4 v = in[i];
            out[2 * i]     = __floats2half2_rn(v.x, v.y);
            out[2 * i + 1] = __floats2half2_rn(v.z, v.w);
        }
        return;
    }

    __shared__ float t[32][33];
    const float* W = (z == 0) ? W0 : (z == 1) ? W1 : (z == 2) ? W2 : W3;
    __half* to = t4 + (size_t)z * HID * HID;

    int n0 = blockIdx.x * 32, k0 = blockIdx.y * 32;
    int tx = threadIdx.x, ty = threadIdx.y;
    #pragma unroll
    for (int r = 0; r < 32; r += 8)
        t[ty + r][tx] = W[(size_t)(k0 + ty + r) * HID + n0 + tx];
    __syncthreads();
    #pragma unroll
    for (int r = 0; r < 32; r += 8)
        to[(size_t)(n0 + ty + r) * HID + k0 + tx] = __float2half_rn(t[tx][ty + r]);
}

// ---------------------------------------------------------------------------
// GEMM machinery (single-term fp16, fp32 accumulate)
// CTA tile 128x64, K-chunk 64, double-buffered. 8 warps = 4(m) x 2(n).
// __launch_bounds__(256, 3): cap regs at 85 so 3 CTAs fit per SM
// (previously 98 regs -> 2 CTAs; occ/issue-bound per ncu round 14).
// ---------------------------------------------------------------------------
#define GKC        64
#define NCHUNK     (HID / GKC)       // 16
#define OFF_B      16384
#define STAGE_BYTES 24576            // A 16K + B 8K
#define GEMM_SMEM  (2 * STAGE_BYTES) // 49152 (static)

__device__ __forceinline__ void gemm_mainloop(uint32_t sb, float c[2][4][4],
    const __half* __restrict__ A, const __half* __restrict__ B,
    int by, int bx, int tid, int lane, int wid)
{
    const int wm = (wid & 3) * 32;
    const int wn = (wid >> 2) * 32;

    const int a_r    = (lane & 7) + ((lane >> 3) & 1) * 8;
    const int a_kb16 = (lane >> 4) * 16;
    const int b_r4   = ((lane >> 4) & 1) * 8 + (lane & 7);
    const int b_kb16 = ((lane >> 3) & 1) * 16;

    // Precomputed per-thread load geometry (SW128 offsets + base pointers)
    uint32_t aso[4]; const __half* ap[4];
    #pragma unroll
    for (int r = 0; r < 4; r++) {
        int u = r * 256 + tid;
        int m = u >> 3, seg = u & 7;
        aso[r] = SW128((uint32_t)(m * 128 + seg * 16));
        ap[r]  = A + (size_t)(by * 128 + m) * HID + seg * 8;
    }
    uint32_t bso[2]; const __half* bp[2];
    #pragma unroll
    for (int r = 0; r < 2; r++) {
        int u = r * 256 + tid;
        int n = u >> 3, seg = u & 7;
        bso[r] = SW128((uint32_t)(n * 128 + seg * 16));
        bp[r]  = B + (size_t)(bx * 64 + n) * HID + seg * 8;
    }

    // Prologue: chunk 0
    #pragma unroll
    for (int r = 0; r < 4; r++) cp16(sb + aso[r], ap[r]);
    #pragma unroll
    for (int r = 0; r < 2; r++) cp16(sb + OFF_B + bso[r], bp[r]);
    CP_COMMIT();

    // Hoisted ldmatrix column constants (row&7 is loop-invariant per thread)
    uint32_t acol[4], bcol[4];
    #pragma unroll
    for (int ks = 0; ks < 4; ks++) {
        acol[ks] = (uint32_t)((ks * 32 + a_kb16) ^ ((a_r & 7) << 4));
        bcol[ks] = (uint32_t)((ks * 32 + b_kb16) ^ ((b_r4 & 7) << 4));
    }

    for (int ch = 0; ch < NCHUNK; ch++) {
        const uint32_t sbase = sb + (ch & 1) * STAGE_BYTES;

        if (ch + 1 < NCHUNK) {
            const uint32_t nb = sb + ((ch + 1) & 1) * STAGE_BYTES;
            const int k0 = (ch + 1) * GKC;
            #pragma unroll
            for (int r = 0; r < 4; r++) cp16(nb + aso[r], ap[r] + k0);
            #pragma unroll
            for (int r = 0; r < 2; r++) cp16(nb + OFF_B + bso[r], bp[r] + k0);
            CP_COMMIT();
            CP_WAIT1();
        } else {
            CP_WAIT0();
        }
        __syncthreads();

        const uint32_t ar0 = sbase + (uint32_t)((wm + a_r) * 128);
        const uint32_t br0 = sbase + OFF_B + (uint32_t)((wn + b_r4) * 128);

        #pragma unroll
        for (int ks = 0; ks < 4; ks++) {
            uint32_t Ah[2][4];
            ldsm4(Ah[0], ar0 + acol[ks]);
            ldsm4(Ah[1], ar0 + 2048 + acol[ks]);   // +16 rows

            #pragma unroll
            for (int ntp = 0; ntp < 2; ntp++) {
                uint32_t Bh[4];
                ldsm4(Bh, br0 + (uint32_t)(ntp * 2048) + bcol[ks]);
                #pragma unroll
                for (int half = 0; half < 2; half++) {
                    int nt = 2 * ntp + half;
                    mma16816(c[0][nt], Ah[0], Bh + 2 * half);
                    mma16816(c[1][nt], Ah[1], Bh + 2 * half);
                }
            }
        }

        __syncthreads();
    }
}

// Fused Q/K/V projection: grid.x = 48 (panel = bx>>4), fp16 output.
__global__ __launch_bounds__(256, 3)
void gemm_qkv(const __half* __restrict__ A, const __half* __restrict__ wt4,
              const float* __restrict__ bq, const float* __restrict__ bk,
              const float* __restrict__ bv,
              __half* __restrict__ q, __half* __restrict__ k, __half* __restrict__ v)
{
    __shared__ __align__(128) char smem[GEMM_SMEM];
    uint32_t sb = smem_u32(smem);
    const int tid  = threadIdx.x;
    const int lane = tid & 31;
    const int wid  = tid >> 5;
    const int panel = blockIdx.x >> 4;
    const int bx    = blockIdx.x & 15;
    const int by    = blockIdx.y;

    const __half* B = wt4 + (size_t)panel * HID * HID;
    const float* bias = (panel == 0) ? bq : (panel == 1) ? bk : bv;
    __half* O = (panel == 0) ? q : (panel == 1) ? k : v;
    const float scale = (panel == 0) ? 0.125f * 1.44269504f : 1.0f;

    float c[2][4][4];
    #pragma unroll
    for (int mt = 0; mt < 2; mt++)
        #pragma unroll
        for (int nt = 0; nt < 4; nt++)
            #pragma unroll
            for (int i = 0; i < 4; i++) c[mt][nt][i] = 0.0f;

    gemm_mainloop(sb, c, A, B, by, bx, tid, lane, wid);

    const int wm = (wid & 3) * 32;
    const int wn = (wid >> 2) * 32;
    const int crow0 = by * 128 + wm + (lane >> 2);
    const int ccol0 = bx * 64 + wn + (lane & 3) * 2;
    #pragma unroll
    for (int nt = 0; nt < 4; nt++) {
        float2 bb = *(const float2*)&bias[ccol0 + nt * 8];
        #pragma unroll
        for (int mt = 0; mt < 2; mt++) {
            #pragma unroll
            for (int h = 0; h < 2; h++) {
                int row = crow0 + mt * 16 + h * 8;
                float vx = (c[mt][nt][2 * h + 0] + bb.x) * scale;
                float vy = (c[mt][nt][2 * h + 1] + bb.y) * scale;
                *(__half2*)&O[(size_t)row * HID + ccol0 + nt * 8] = __floats2half2_rn(vx, vy);
            }
        }
    }
}

// O-projection GEMM: fp32 output + bias.
__global__ __launch_bounds__(256, 3)
void gemm_out(const __half* __restrict__ A, const __half* __restrict__ B,
              const float* __restrict__ bias, float* __restrict__ Cf)
{
    __shared__ __align__(128) char smem[GEMM_SMEM];
    uint32_t sb = smem_u32(smem);
    const int tid  = threadIdx.x;
    const int lane = tid & 31;
    const int wid  = tid >> 5;
    const int bx = blockIdx.x, by = blockIdx.y;

    float c[2][4][4];
    #pragma unroll
    for (int mt = 0; mt < 2; mt++)
        #pragma unroll
        for (int nt = 0; nt < 4; nt++)
            #pragma unroll
            for (int i = 0; i < 4; i++) c[mt][nt][i] = 0.0f;

    gemm_mainloop(sb, c, A, B, by, bx, tid, lane, wid);

    const int wm = (wid & 3) * 32;
    const int wn = (wid >> 2) * 32;
    const int crow0 = by * 128 + wm + (lane >> 2);
    const int ccol0 = bx * 64 + wn + (lane & 3) * 2;
    #pragma unroll
    for (int nt = 0; nt < 4; nt++) {
        float2 bb = *(const float2*)&bias[ccol0 + nt * 8];
        #pragma unroll
        for (int mt = 0; mt < 2; mt++) {
            #pragma unroll
            for (int h = 0; h < 2; h++) {
                int row = crow0 + mt * 16 + h * 8;
                float2 v;
                v.x = c[mt][nt][2 * h + 0] + bb.x;
                v.y = c[mt][nt][2 * h + 1] + bb.y;
                *(float2*)&Cf[(size_t)row * HID + ccol0 + nt * 8] = v;
            }
        }
    }
}

// ---------------------------------------------------------------------------
// fp16 tensor-core flash attention, 64-key tiles, double-buffered K/V.
// Per CTA: 128 queries x one (b,h). 8 warps x 16 query rows (256 threads).
// smem: Q 16K + 2 stages x (K 8K + V 8K) = 48K static.
// ---------------------------------------------------------------------------
#define KT     64
#define ATT_Q   0
#define ATT_STG0 16384
#define ATT_STG_SZ 16384
#define ATT_V_OFF 8192
#define ATT_SMEM 49152

__global__ __launch_bounds__(256, 2)
void flash_attn_mma(const __half* __restrict__ Q, const __half* __restrict__ K,
                    const __half* __restrict__ V, __half* __restrict__ C)
{
    __shared__ __align__(128) char smem[ATT_SMEM];
    uint32_t sb = smem_u32(smem);
    const int tid  = threadIdx.x;
    const int lane = tid & 31;
    const int wid  = tid >> 5;
    const int q0 = blockIdx.x * 128;
    const int h  = blockIdx.y;
    const int b  = blockIdx.z;

    const size_t qg  = ((size_t)(b * SEQ + q0)) * HID + h * HDIM;
    const size_t kvg = ((size_t)(b * SEQ)) * HID + h * HDIM;

    // ---- Q load ----
    {
        #pragma unroll
        for (int r = 0; r < 4; r++) {
            int u = r * 256 + tid;
            int row = u >> 3, seg = u & 7;
            uint32_t so = SW128((uint32_t)(row * 128 + seg * 16));
            cp16(sb + ATT_Q + so, Q + qg + (size_t)row * HID + seg * 8);
        }
    }
    CP_COMMIT();

    // K/V load geometry
    uint32_t kvso[2];
    const __half* kp[2];
    const __half* vp[2];
    #pragma unroll
    for (int r = 0; r < 2; r++) {
        int u = r * 256 + tid;
        int row = u >> 3, seg = u & 7;
        kvso[r] = SW128((uint32_t)(row * 128 + seg * 16));
        size_t off = kvg + (size_t)row * HID + seg * 8;
        kp[r] = K + off;
        vp[r] = V + off;
    }

    // KV tile 0 -> stage 0
    #pragma unroll
    for (int r = 0; r < 2; r++) {
        cp16(sb + ATT_STG0 + kvso[r], kp[r]);
        cp16(sb + ATT_STG0 + ATT_V_OFF + kvso[r], vp[r]);
    }
    CP_COMMIT();
    #pragma unroll
    for (int r = 0; r < 2; r++) { kp[r] += KT * HID; vp[r] += KT * HID; }

    const int wm = wid * 16;
    const int a_r    = (lane & 7) + ((lane >> 3) & 1) * 8;
    const int a_kb16 = (lane >> 4) * 16;
    const int b_r    = lane & 7;
    const int b_kb16 = ((lane >> 3) & 1) * 16;

    // Hoisted ldmatrix geometry
    uint32_t kcol[4];
    #pragma unroll
    for (int kc = 0; kc < 4; kc++)
        kcol[kc] = (uint32_t)((kc * 32 + b_kb16) ^ ((b_r & 7) << 4));
    const uint32_t krow0 = (uint32_t)((((lane >> 4) & 1) * 8 + b_r) * 128);
    uint32_t vcol[4];
    #pragma unroll
    for (int ntv = 0; ntv < 4; ntv++)
        vcol[ntv] = (uint32_t)((ntv * 32 + 16 * (lane >> 4)) ^ ((lane & 7) << 4));
    const uint32_t vrow0 = (uint32_t)((lane & 15) * 128);

    CP_WAIT1();              // Q resident
    __syncthreads();

    // Cache Q A-fragments
    uint32_t qh[4][4];
    #pragma unroll
    for (int kc = 0; kc < 4; kc++) {
        int row = wm + a_r;
        uint32_t col = (uint32_t)((kc * 32 + a_kb16) ^ ((row & 7) << 4));
        ldsm4(qh[kc], sb + ATT_Q + (uint32_t)(row * 128) + col);
    }

    float m0 = -INFINITY, m1 = -INFINITY, l0 = 0.0f, l1 = 0.0f;
    float o[8][4];
    #pragma unroll
    for (int nt = 0; nt < 8; nt++)
        #pragma unroll
        for (int i = 0; i < 4; i++) o[nt][i] = 0.0f;

    for (int kt = 0; kt < SEQ / KT; kt++) {
        if (kt + 1 < SEQ / KT) {
            const uint32_t nstg = sb + ATT_STG0 + ((kt + 1) & 1) * ATT_STG_SZ;
            #pragma unroll
            for (int r = 0; r < 2; r++) {
                cp16(nstg + kvso[r], kp[r]);
                cp16(nstg + ATT_V_OFF + kvso[r], vp[r]);
            }
            CP_COMMIT();
            #pragma unroll
            for (int r = 0; r < 2; r++) { kp[r] += KT * HID; vp[r] += KT * HID; }
            CP_WAIT1();
        } else {
            CP_WAIT0();
        }
        __syncthreads();

        const uint32_t stg = sb + ATT_STG0 + (kt & 1) * ATT_STG_SZ;
        const uint32_t kbase = stg + krow0;
        const uint32_t vbase = stg + ATT_V_OFF + vrow0;

        // ---- S = Q @ K^T ----
        float s[8][4];
        #pragma unroll
        for (int nt = 0; nt < 8; nt++)
            #pragma unroll
            for (int i = 0; i < 4; i++) s[nt][i] = 0.0f;

        #pragma unroll
        for (int kc = 0; kc < 4; kc++) {
            #pragma unroll
            for (int ntp = 0; ntp < 4; ntp++) {
                uint32_t kh[4];
                ldsm4(kh, kbase + (uint32_t)(ntp * 2048) + kcol[kc]);
                mma16816(s[2 * ntp],     qh[kc], kh);
                mma16816(s[2 * ntp + 1], qh[kc], kh + 2);
            }
        }

        // ---- Online softmax (base-2) ----
        float rmax0 = -INFINITY, rmax1 = -INFINITY;
        #pragma unroll
        for (int nt = 0; nt < 8; nt++) {
            rmax0 = fmaxf(rmax0, fmaxf(s[nt][0], s[nt][1]));
            rmax1 = fmaxf(rmax1, fmaxf(s[nt][2], s[nt][3]));
        }
        rmax0 = fmaxf(rmax0, __shfl_xor_sync(0xffffffffu, rmax0, 1));
        rmax0 = fmaxf(rmax0, __shfl_xor_sync(0xffffffffu, rmax0, 2));
        rmax1 = fmaxf(rmax1, __shfl_xor_sync(0xffffffffu, rmax1, 1));
        rmax1 = fmaxf(rmax1, __shfl_xor_sync(0xffffffffu, rmax1, 2));

        if (rmax0 > m0) {
            float f0 = ex2(m0 - rmax0);
            m0 = rmax0;
            l0 *= f0;
            #pragma unroll
            for (int nt = 0; nt < 8; nt++) { o[nt][0] *= f0; o[nt][1] *= f0; }
        }
        if (rmax1 > m1) {
            float f1 = ex2(m1 - rmax1);
            m1 = rmax1;
            l1 *= f1;
            #pragma unroll
            for (int nt = 0; nt < 8; nt++) { o[nt][2] *= f1; o[nt][3] *= f1; }
        }

        float ls0 = 0.0f, ls1 = 0.0f;
        #pragma unroll
        for (int nt = 0; nt < 8; nt++) {
            s[nt][0] = ex2(s[nt][0] - m0);
            s[nt][1] = ex2(s[nt][1] - m0);
            s[nt][2] = ex2(s[nt][2] - m1);
            s[nt][3] = ex2(s[nt][3] - m1);
            ls0 += s[nt][0] + s[nt][1];
            ls1 += s[nt][2] + s[nt][3];
        }
        ls0 += __shfl_xor_sync(0xffffffffu, ls0, 1);
        ls0 += __shfl_xor_sync(0xffffffffu, ls0, 2);
        ls1 += __shfl_xor_sync(0xffffffffu, ls1, 1);
        ls1 += __shfl_xor_sync(0xffffffffu, ls1, 2);
        l0 += ls0;
        l1 += ls1;

        // ---- P pack + PV MMAs ----
        #pragma unroll
        for (int kj = 0; kj < 4; kj++) {
            uint32_t phi[4];
            #pragma unroll
            for (int half = 0; half < 2; half++) {
                int t = 2 * kj + half;
                __half2 h0 = __floats2half2_rn(s[t][0], s[t][1]);
                __half2 h1 = __floats2half2_rn(s[t][2], s[t][3]);
                phi[2 * half + 0] = *(uint32_t*)&h0;
                phi[2 * half + 1] = *(uint32_t*)&h1;
            }
            #pragma unroll
            for (int ntv = 0; ntv < 4; ntv++) {
                uint32_t vh[4];
                ldsm4t(vh, vbase + (uint32_t)(kj * 2048) + vcol[ntv]);
                mma16816(o[2 * ntv],     phi, vh);
                mma16816(o[2 * ntv + 1], phi, vh + 2);
            }
        }

        __syncthreads();
    }

    // ---- Finalize ----
    const float inv0 = 1.0f / l0, inv1 = 1.0f / l1;
    const int row0 = q0 + wm + (lane >> 2);
    const int colb = (lane & 3) * 2;
    #pragma unroll
    for (int nt = 0; nt < 8; nt++) {
        {
            size_t idx = ((size_t)(b * SEQ + row0)) * HID + h * HDIM + nt * 8 + colb;
            *(__half2*)&C[idx] = __floats2half2_rn(o[nt][0] * inv0, o[nt][1] * inv0);
        }
        {
            size_t idx = ((size_t)(b * SEQ + row0 + 8)) * HID + h * HDIM + nt * 8 + colb;
            *(__half2*)&C[idx] = __floats2half2_rn(o[nt][2] * inv1, o[nt][3] * inv1);
        }
    }
}

// ---------------------------------------------------------------------------
// Launch (no cudaFuncSetAttribute, no dynamic smem)
// ---------------------------------------------------------------------------
extern "C" void kernel_launch(void* const* d_in, const int* in_sizes, int n_in,
                              void* d_out, int out_size)
{
    const float* x  = (const float*)d_in[0];
    const float* Wq = (const float*)d_in[1];
    const float* bq = (const float*)d_in[2];
    const float* Wk = (const float*)d_in[3];
    const float* bk = (const float*)d_in[4];
    const float* Wv = (const float*)d_in[5];
    const float* bv = (const float*)d_in[6];
    const float* Wo = (const float*)d_in[7];
    const float* bo = (const float*)d_in[8];
    float* out = (float*)d_out;

    __half *xh, *qh, *kh, *vh, *ch, *wt4;
    cudaGetSymbolAddress((void**)&xh, g_xh);
    cudaGetSymbolAddress((void**)&qh, g_qh);
    cudaGetSymbolAddress((void**)&kh, g_kh);
    cudaGetSymbolAddress((void**)&vh, g_vh);
    cudaGetSymbolAddress((void**)&ch, g_ch);
    cudaGetSymbolAddress((void**)&wt4, g_wt4);

    dim3 cvg(HID / 32, HID / 32, 5);
    dim3 cvb(32, 8);
    convert_all<<<cvg, cvb>>>(x, Wq, Wk, Wv, Wo, xh, wt4);

    dim3 qkvgrid(48, MROWS / 128);   // (48, 64): 3 panels x 16 n-tiles
    gemm_qkv<<<qkvgrid, 256>>>(xh, wt4, bq, bk, bv, qh, kh, vh);

    dim3 agrid(SEQ / 128, NHEAD, BATCH);   // (8, 16, 8)
    flash_attn_mma<<<agrid, 256>>>(qh, kh, vh, ch);

    dim3 ogrid(HID / 64, MROWS / 128);    // (16, 64)
    gemm_out<<<ogrid, 256>>>(ch, wt4 + (size_t)3 * HID * HID, bo, out);
}